// round 2
// baseline (speedup 1.0000x reference)
#include <cuda_runtime.h>

// SiluAndMul: x [M, 2N] fp32 -> out [M, N] fp32, out = silu(x[:, :N]) * x[:, N:]
// M = 16384, N = 11008. Pure HBM-bound: 2.164 GB traffic, floor ~270us @ 8TB/s.
// R2: 2x float4 per thread (front-batched loads, MLP_p1=4) + streaming cache hints.

static constexpr int M = 16384;
static constexpr int N = 11008;         // output cols
static constexpr int TWO_N = 2 * N;     // input row stride (floats)
static constexpr int N4 = N / 4;        // 2752 float4 per output row
static constexpr int BLOCK = 256;
static constexpr int COLS_PER_BLOCK = 2 * BLOCK;              // 512 float4 cols
static constexpr int GRID_X = (N4 + COLS_PER_BLOCK - 1) / COLS_PER_BLOCK;  // 6

__device__ __forceinline__ float silu(float g) {
    return g * __frcp_rn(1.0f + __expf(-g));
}

__global__ __launch_bounds__(BLOCK) void silu_and_mul_kernel(
    const float* __restrict__ x, float* __restrict__ out)
{
    const long long row = blockIdx.y;
    const int c0 = blockIdx.x * COLS_PER_BLOCK + threadIdx.x;  // float4 col idx
    const int c1 = c0 + BLOCK;

    const float4* gate4 = reinterpret_cast<const float4*>(x + row * TWO_N);
    const float4* up4   = reinterpret_cast<const float4*>(x + row * TWO_N + N);
    float4* out4        = reinterpret_cast<float4*>(out + row * (long long)N);

    const bool p0 = (c0 < N4);
    const bool p1 = (c1 < N4);

    // Front-batch all 4 loads for MLP before any dependent compute.
    float4 g0, g1, u0, u1;
    if (p0) g0 = __ldcs(&gate4[c0]);
    if (p1) g1 = __ldcs(&gate4[c1]);
    if (p0) u0 = __ldcs(&up4[c0]);
    if (p1) u1 = __ldcs(&up4[c1]);

    if (p0) {
        float4 r;
        r.x = silu(g0.x) * u0.x;
        r.y = silu(g0.y) * u0.y;
        r.z = silu(g0.z) * u0.z;
        r.w = silu(g0.w) * u0.w;
        __stcs(&out4[c0], r);
    }
    if (p1) {
        float4 r;
        r.x = silu(g1.x) * u1.x;
        r.y = silu(g1.y) * u1.y;
        r.z = silu(g1.z) * u1.z;
        r.w = silu(g1.w) * u1.w;
        __stcs(&out4[c1], r);
    }
}

extern "C" void kernel_launch(void* const* d_in, const int* in_sizes, int n_in,
                              void* d_out, int out_size)
{
    const float* x = (const float*)d_in[0];
    float* out = (float*)d_out;

    dim3 block(BLOCK);
    dim3 grid(GRID_X, M);   // (6, 16384)
    silu_and_mul_kernel<<<grid, block>>>(x, out);
}